// round 9
// baseline (speedup 1.0000x reference)
#include <cuda_runtime.h>

#define BS    64
#define SL    8192
#define EDIM  64
#define DDIM  64
#define VOCAB 1088
#define NVAL  64
#define NTILE 17
#define SPLIT 8
#define CHUNK (SL / SPLIT)          // 1024
#define EPT   4                     // int4 per thread

// Scratch (no allocations allowed)
__device__ float g_EK[BS * VOCAB];   // exp(SK)
__device__ float g_EV[BS * NVAL];    // exp(SV)
__device__ float g_Pb[BS * SPLIT * NVAL];
__device__ int   g_cnt[BS];   // zero-init; self-reset by combining block

// ---------------------------------------------------------------------------
// Kernel A v3: grid = 64 batches x 17 vocab-tiles (1088 blocks), 128 threads.
// Every block prefetches its embK tile (32 floats/thread) and Wq half-row
// into registers at cycle 0, then runs the short dependent chain:
//   q -> eqs -> Q -> Qk -> EK = exp(tile . Qk)
// Redundant Q/Qk per block (~9 KFLOP) is free; latency overlap is the win.
// Thread layout: tid = v(0..63) + 64*h(0..1); thread covers e-range h*32..+31.
// ---------------------------------------------------------------------------
__global__ __launch_bounds__(128) void tables_kernel(
    const int*   __restrict__ q,
    const float* __restrict__ embK,
    const float* __restrict__ Wk_w,   // (64, 128) row-major
    const float* __restrict__ Wq_w,   // (64, 64) row-major
    const float* __restrict__ Wq_b)
{
    const int bid  = blockIdx.x;
    const int b    = bid / NTILE;
    const int tile = bid % NTILE;
    const int v0   = tile * 64;
    const int tid  = threadIdx.x;
    const int v    = tid & 63;
    const int h    = tid >> 6;         // e-half: 0 -> e[0..31], 1 -> e[32..63]

    __shared__ float eqs[EDIM];
    __shared__ float Qs [DDIM];
    __shared__ float Qks[EDIM];
    __shared__ float part[128];

    // ---- Prefetch (no deps): embK tile half-row + Wq half-row ----
    float4 te[8];                      // embK[v0+v][h*32 .. h*32+31]
    {
        const float4* src = reinterpret_cast<const float4*>(
            embK + (size_t)(v0 + v) * EDIM + h * 32);
        #pragma unroll
        for (int i = 0; i < 8; i++) te[i] = src[i];
    }
    float4 wq[8];                      // Wq_w[d=v][h*32 .. +31] (d == v lane map)
    {
        const float4* src = reinterpret_cast<const float4*>(
            Wq_w + (size_t)v * EDIM + h * 32);
        #pragma unroll
        for (int i = 0; i < 8; i++) wq[i] = src[i];
    }

    // ---- eqs: dependent chain q[b] -> embK row ----
    if (tid < EDIM) eqs[tid] = embK[(size_t)q[b] * EDIM + tid];
    __syncthreads();

    // ---- Q: thread (d=v, half=h) -> 32-wide partial on prefetched wq ----
    {
        float acc = 0.f;
        #pragma unroll
        for (int i = 0; i < 8; i++) {
            const int e = h * 32 + i * 4;
            acc += wq[i].x * eqs[e] + wq[i].y * eqs[e + 1]
                 + wq[i].z * eqs[e + 2] + wq[i].w * eqs[e + 3];
        }
        part[tid] = acc;
    }
    __syncthreads();
    if (tid < DDIM)
        Qs[tid] = part[tid] + part[tid + 64] + Wq_b[tid];
    __syncthreads();

    // ---- Qk: thread (e=v, dg=h) -> 32-d partial (coalesced Wk columns) ----
    {
        float acc = 0.f;
        #pragma unroll
        for (int i = 0; i < 32; i++) {
            const int d = h * 32 + i;
            acc = fmaf(Wk_w[(size_t)d * 128 + 64 + v], Qs[d], acc);
        }
        part[tid] = acc;
    }
    __syncthreads();
    if (tid < EDIM)
        Qks[tid] = (part[tid] + part[tid + 64]) * 0.125f;

    // ---- EV: tile==0 blocks only (block-uniform; syncs match) ----
    if (tile == 0) {
        __syncthreads();
        float acc = 0.f;
        #pragma unroll
        for (int i = 0; i < 32; i++) {
            const int d = h * 32 + i;
            acc = fmaf(Wk_w[(size_t)d * 128 + v], Qs[d], acc);
        }
        part[tid] = acc;
        __syncthreads();
        if (tid < NVAL)
            g_EV[b * NVAL + tid] = __expf((part[tid] + part[tid + 64]) * 0.125f);
    }
    __syncthreads();                   // Qks ready

    // ---- EK: registers x Qks, 2-way shared reduce, exp, coalesced write ----
    {
        float acc = 0.f;
        #pragma unroll
        for (int i = 0; i < 8; i++) {
            const int e = h * 32 + i * 4;
            acc += te[i].x * Qks[e] + te[i].y * Qks[e + 1]
                 + te[i].z * Qks[e + 2] + te[i].w * Qks[e + 3];
        }
        part[tid] = acc;
    }
    __syncthreads();
    if (tid < 64)
        g_EK[(size_t)b * VOCAB + v0 + tid] = __expf(part[tid] + part[tid + 64]);
}

// ---------------------------------------------------------------------------
// Kernel B: pure gather-histogram (byte-identical to R8 best: 8.38us).
// ---------------------------------------------------------------------------
__global__ __launch_bounds__(256) void attn_kernel(
    const int* __restrict__ x,
    float*     __restrict__ out)
{
    const int b    = blockIdx.x >> 3;
    const int sp   = blockIdx.x & 7;
    const int tid  = threadIdx.x;
    const int warp = tid >> 5;

    __shared__ float EKs[VOCAB];
    __shared__ float bins[8][NVAL];     // warp-replicated histograms
    __shared__ float num[NVAL];
    __shared__ int   lastFlag;

    // Prefetch index data first (DRAM) — overlaps table fill (L2)
    const int* kp = x + (size_t)b * 2 * SL + sp * CHUNK;
    const int* vp = kp + SL;
    const int4 k4 = __ldg(reinterpret_cast<const int4*>(kp) + tid);
    const int4 w4 = __ldg(reinterpret_cast<const int4*>(vp) + tid);

    // Table fill (vectorized, from L2)
    {
        const float4* src = reinterpret_cast<const float4*>(g_EK + (size_t)b * VOCAB);
        float4* dst = reinterpret_cast<float4*>(EKs);
        for (int i = tid; i < VOCAB / 4; i += 256) dst[i] = src[i];
    }
    for (int i = tid; i < 8 * NVAL; i += 256) (&bins[0][0])[i] = 0.f;
    __syncthreads();

    const int kk[EPT] = {k4.x, k4.y, k4.z, k4.w};
    const int vv[EPT] = {w4.x - NVAL, w4.y - NVAL, w4.z - NVAL, w4.w - NVAL};

    #pragma unroll
    for (int i = 0; i < EPT; i++)
        atomicAdd(&bins[warp][vv[i]], EKs[kk[i]]);
    __syncthreads();

    if (tid < NVAL) {
        float bsum = 0.f;
        #pragma unroll
        for (int w = 0; w < 8; w++) bsum += bins[w][tid];
        g_Pb[(b * SPLIT + sp) * NVAL + tid] = bsum;
    }
    __syncthreads();

    if (tid == 0) {
        __threadfence();                            // publish partials (release)
        const int old = atomicAdd(&g_cnt[b], 1);
        lastFlag = (old == SPLIT - 1) ? 1 : 0;
        __threadfence();                            // acquire
    }
    __syncthreads();

    if (lastFlag) {
        if (tid < NVAL) {
            volatile float* vPb = g_Pb + (size_t)b * SPLIT * NVAL;
            float s = 0.f;
            #pragma unroll
            for (int s2 = 0; s2 < SPLIT; s2++) s += vPb[s2 * NVAL + tid];
            num[tid] = s * g_EV[b * NVAL + tid];
        }
        __syncthreads();
        if (tid < 32) {
            float zz = num[tid] + num[tid + 32];
            #pragma unroll
            for (int o = 16; o > 0; o >>= 1) zz += __shfl_xor_sync(0xffffffffu, zz, o);
            if (tid == 0) num[0] = __frcp_rn(zz);   // stash 1/Z in num[0]
        }
        __syncthreads();
        if (tid < NVAL) {
            float val = (tid == 0) ? 0.f : num[tid];
            float rcpZ = num[0];
            if (tid == 0) {
                volatile float* vPb = g_Pb + (size_t)b * SPLIT * NVAL;
                float s = 0.f;
                #pragma unroll
                for (int s2 = 0; s2 < SPLIT; s2++) s += vPb[s2 * NVAL];
                val = s * g_EV[b * NVAL];           // recompute overwritten num[0]
            }
            out[b * NVAL + tid] = val * rcpZ;
        }
        __syncthreads();
        if (tid == 0) g_cnt[b] = 0;                 // re-arm for next replay
    }
}

// ---------------------------------------------------------------------------
// Inputs (metadata order): x(int32), q(int32), embK, Wk_w, Wk_b, Wq_w, Wq_b.
// Wk_b is softmax-invariant (constant per batch) and intentionally unused.
// ---------------------------------------------------------------------------
extern "C" void kernel_launch(void* const* d_in, const int* in_sizes, int n_in,
                              void* d_out, int out_size)
{
    const int*   x    = (const int*)  d_in[0];
    const int*   q    = (const int*)  d_in[1];
    const float* embK = (const float*)d_in[2];
    const float* Wk_w = (const float*)d_in[3];
    const float* Wq_w = (const float*)d_in[5];
    const float* Wq_b = (const float*)d_in[6];
    float* out = (float*)d_out;

    tables_kernel<<<BS * NTILE, 128>>>(q, embK, Wk_w, Wq_w, Wq_b);
    attn_kernel<<<BS * SPLIT, 256>>>(x, out);
}

// round 10
// speedup vs baseline: 1.1119x; 1.1119x over previous
#include <cuda_runtime.h>

#define BS    64
#define SL    8192
#define EDIM  64
#define DDIM  64
#define VOCAB 1088
#define NVAL  64
#define SPLIT 8
#define CHUNK (SL / SPLIT)          // 1024
#define ATHR  128                   // attn threads/block
#define EPT   8                     // elements per thread (2x int4)

// Scratch (no allocations allowed)
__device__ float g_EK[BS * VOCAB];   // exp(SK)
__device__ float g_EV[BS * NVAL];    // exp(SV)
__device__ float g_Pb[BS * SPLIT * NVAL];
__device__ int   g_cnt[BS];   // zero-init; self-reset by combining block

// ---------------------------------------------------------------------------
// Kernel A: per-batch score tables (EXACT R8 version — best measured).
// grid = 64 batches x 4 tile-groups, 256 threads.
// ---------------------------------------------------------------------------
__global__ __launch_bounds__(256) void tables_kernel(
    const int*   __restrict__ q,
    const float* __restrict__ embK,
    const float* __restrict__ Wk_w,   // (64, 128) row-major
    const float* __restrict__ Wq_w,   // (64, 64) row-major
    const float* __restrict__ Wq_b)
{
    const int b   = blockIdx.x >> 2;
    const int tg  = blockIdx.x & 3;
    const int tid = threadIdx.x;

    __shared__ float eqs[EDIM];
    __shared__ float Qs [DDIM];
    __shared__ float Qks[EDIM];
    __shared__ float part[256];
    __shared__ float tile[64 * 65];

    if (tid < EDIM) eqs[tid] = embK[(size_t)q[b] * EDIM + tid];
    __syncthreads();

    {
        const int d = tid >> 2, s = tid & 3;
        const float4* wrow = reinterpret_cast<const float4*>(Wq_w + (size_t)d * EDIM) + s * 4;
        float acc = 0.f;
        #pragma unroll
        for (int i = 0; i < 4; i++) {
            const float4 w4 = wrow[i];
            const int e = s * 16 + i * 4;
            acc += w4.x * eqs[e] + w4.y * eqs[e + 1] + w4.z * eqs[e + 2] + w4.w * eqs[e + 3];
        }
        part[tid] = acc;
    }
    __syncthreads();
    if (tid < DDIM)
        Qs[tid] = part[tid * 4] + part[tid * 4 + 1] + part[tid * 4 + 2] + part[tid * 4 + 3]
                + Wq_b[tid];
    __syncthreads();

    {
        const int dg = tid >> 6, e = tid & 63;
        float acc = 0.f;
        #pragma unroll
        for (int i = 0; i < 16; i++) {
            const int d = dg * 16 + i;
            acc = fmaf(Wk_w[(size_t)d * 128 + 64 + e], Qs[d], acc);
        }
        part[tid] = acc;
    }
    __syncthreads();
    if (tid < EDIM)
        Qks[tid] = (part[tid] + part[64 + tid] + part[128 + tid] + part[192 + tid]) * 0.125f;

    if (tg == 0) {
        __syncthreads();
        const int dg = tid >> 6, e = tid & 63;
        float acc = 0.f;
        #pragma unroll
        for (int i = 0; i < 16; i++) {
            const int d = dg * 16 + i;
            acc = fmaf(Wk_w[(size_t)d * 128 + e], Qs[d], acc);
        }
        part[tid] = acc;
        __syncthreads();
        if (tid < NVAL)
            g_EV[b * NVAL + tid] =
                __expf((part[tid] + part[64 + tid] + part[128 + tid] + part[192 + tid]) * 0.125f);
    }
    __syncthreads();

    const int qtr = tid >> 6, v = tid & 63;
    float qk[16];
    #pragma unroll
    for (int i = 0; i < 16; i++) qk[i] = Qks[qtr * 16 + i];

    const int ntiles = (tg == 0) ? 5 : 4;
    for (int t = 0; t < ntiles; t++) {
        const int tile_id = (t < 4) ? (tg * 4 + t) : 16;
        const int v0 = tile_id * 64;

        __syncthreads();
        for (int i = tid; i < 4096; i += 256)
            tile[(i >> 6) * 65 + (i & 63)] = embK[(size_t)v0 * EDIM + i];
        __syncthreads();

        float acc = 0.f;
        #pragma unroll
        for (int i = 0; i < 16; i++)
            acc = fmaf(tile[v * 65 + qtr * 16 + i], qk[i], acc);
        part[qtr * 64 + v] = acc;
        __syncthreads();

        if (tid < 64)
            g_EK[(size_t)b * VOCAB + v0 + tid] =
                __expf(part[tid] + part[64 + tid] + part[128 + tid] + part[192 + tid]);
    }
}

// ---------------------------------------------------------------------------
// Kernel B: ATOMIC-FREE gather-histogram.
// Each thread owns a private bin column tb[tid][0..63] (stride 65 => bank =
// (tid+n)%32: conflict-free updates AND reduction). No shared atomics at all.
// grid = 64 batches x 8 splits (512 blocks), 128 threads, 8 elems/thread.
// ---------------------------------------------------------------------------
__global__ __launch_bounds__(ATHR) void attn_kernel(
    const int* __restrict__ x,
    float*     __restrict__ out)
{
    const int b   = blockIdx.x >> 3;
    const int sp  = blockIdx.x & 7;
    const int tid = threadIdx.x;

    __shared__ float EKs[VOCAB];
    __shared__ float tb[ATHR * 65];     // per-thread bin columns, padded
    __shared__ float red2[ATHR];
    __shared__ float num[NVAL];
    __shared__ int   lastFlag;

    // Prefetch index data first (DRAM) — overlaps table fill (L2)
    const int* kp = x + (size_t)b * 2 * SL + sp * CHUNK;
    const int* vp = kp + SL;
    const int4 ka = __ldg(reinterpret_cast<const int4*>(kp) + tid);
    const int4 kb = __ldg(reinterpret_cast<const int4*>(kp) + tid + ATHR);
    const int4 wa = __ldg(reinterpret_cast<const int4*>(vp) + tid);
    const int4 wb = __ldg(reinterpret_cast<const int4*>(vp) + tid + ATHR);

    // EK table fill (vectorized, from L2)
    {
        const float4* src = reinterpret_cast<const float4*>(g_EK + (size_t)b * VOCAB);
        float4* dst = reinterpret_cast<float4*>(EKs);
        for (int i = tid; i < VOCAB / 4; i += ATHR) dst[i] = src[i];
    }
    // Zero own bin column (conflict-free across lanes)
    {
        float* col = tb + tid * 65;
        #pragma unroll
        for (int n = 0; n < NVAL; n++) col[n] = 0.f;
    }
    __syncthreads();

    const int kk[EPT] = {ka.x, ka.y, ka.z, ka.w, kb.x, kb.y, kb.z, kb.w};
    const int vv[EPT] = {wa.x - NVAL, wa.y - NVAL, wa.z - NVAL, wa.w - NVAL,
                         wb.x - NVAL, wb.y - NVAL, wb.z - NVAL, wb.w - NVAL};

    {
        float* col = tb + tid * 65;
        #pragma unroll
        for (int i = 0; i < EPT; i++)
            col[vv[i]] += EKs[kk[i]];   // plain LDS/FADD/STS, no atomics
    }
    __syncthreads();

    // Reduce 128 columns -> 64 bins. Thread (n = tid&63, hh = tid>>6) sums
    // half the columns; pair-added below. All accesses conflict-free.
    {
        const int n = tid & 63, hh = tid >> 6;
        float s = 0.f;
        #pragma unroll 8
        for (int t = 0; t < ATHR / 2; t++)
            s += tb[(hh * (ATHR / 2) + t) * 65 + n];
        red2[tid] = s;
    }
    __syncthreads();

    if (tid < NVAL)
        g_Pb[(b * SPLIT + sp) * NVAL + tid] = red2[tid] + red2[tid + 64];
    __syncthreads();

    if (tid == 0) {
        __threadfence();                            // publish partials (release)
        const int old = atomicAdd(&g_cnt[b], 1);
        lastFlag = (old == SPLIT - 1) ? 1 : 0;
        __threadfence();                            // acquire
    }
    __syncthreads();

    if (lastFlag) {
        if (tid < NVAL) {
            volatile float* vPb = g_Pb + (size_t)b * SPLIT * NVAL;
            float s = 0.f;
            #pragma unroll
            for (int s2 = 0; s2 < SPLIT; s2++) s += vPb[s2 * NVAL + tid];
            num[tid] = s * g_EV[b * NVAL + tid];
        }
        __syncthreads();
        if (tid < 32) {
            float zz = num[tid] + num[tid + 32];
            #pragma unroll
            for (int o = 16; o > 0; o >>= 1) zz += __shfl_xor_sync(0xffffffffu, zz, o);
            if (tid == 0) num[0] = __frcp_rn(zz);   // stash 1/Z in num[0]
        }
        __syncthreads();
        if (tid < NVAL) {
            float val = (tid == 0) ? 0.f : num[tid];
            float rcpZ = num[0];
            if (tid == 0) {
                volatile float* vPb = g_Pb + (size_t)b * SPLIT * NVAL;
                float s = 0.f;
                #pragma unroll
                for (int s2 = 0; s2 < SPLIT; s2++) s += vPb[s2 * NVAL];
                val = s * g_EV[b * NVAL];           // recompute overwritten num[0]
            }
            out[b * NVAL + tid] = val * rcpZ;
        }
        __syncthreads();
        if (tid == 0) g_cnt[b] = 0;                 // re-arm for next replay
    }
}

// ---------------------------------------------------------------------------
// Inputs (metadata order): x(int32), q(int32), embK, Wk_w, Wk_b, Wq_w, Wq_b.
// Wk_b is softmax-invariant (constant per batch) and intentionally unused.
// ---------------------------------------------------------------------------
extern "C" void kernel_launch(void* const* d_in, const int* in_sizes, int n_in,
                              void* d_out, int out_size)
{
    const int*   x    = (const int*)  d_in[0];
    const int*   q    = (const int*)  d_in[1];
    const float* embK = (const float*)d_in[2];
    const float* Wk_w = (const float*)d_in[3];
    const float* Wq_w = (const float*)d_in[5];
    const float* Wq_b = (const float*)d_in[6];
    float* out = (float*)d_out;

    tables_kernel<<<BS * 4, 256>>>(q, embK, Wk_w, Wq_w, Wq_b);
    attn_kernel<<<BS * SPLIT, ATHR>>>(x, out);
}

// round 11
// speedup vs baseline: 1.3875x; 1.2479x over previous
#include <cuda_runtime.h>

#define BS    64
#define SL    8192
#define EDIM  64
#define DDIM  64
#define VOCAB 1088
#define NVAL  64
#define NTILE 17
#define SPLIT 8
#define CHUNK (SL / SPLIT)          // 1024
#define EPT   4

// Scratch (no allocations allowed)
__device__ float g_Qk[BS * EDIM];
__device__ float g_EV[BS * NVAL];
__device__ float g_EK[BS * VOCAB];
__device__ float g_num[BS * NVAL];   // zero-init; reset by combining block
__device__ int   g_cnt[BS];          // zero-init; reset by combining block

// ---------------------------------------------------------------------------
// A1: Q, Qk, EV per batch. 64 blocks x 256 threads. One short dependent chain.
//   Q[d]  = embK[q[b]] . Wq_w[d,:] + Wq_b[d]
//   Qk[e] = 0.125 * sum_d Wk_w[d,64+e] * Q[d]
//   EV[n] = exp(0.125 * sum_d Wk_w[d,n] * Q[d])
// ---------------------------------------------------------------------------
__global__ __launch_bounds__(256) void qk_kernel(
    const int*   __restrict__ q,
    const float* __restrict__ embK,
    const float* __restrict__ Wk_w,   // (64, 128) row-major
    const float* __restrict__ Wq_w,   // (64, 64) row-major
    const float* __restrict__ Wq_b)
{
    const int b   = blockIdx.x;
    const int tid = threadIdx.x;

    __shared__ float eqs[EDIM];
    __shared__ float Qs [DDIM];
    __shared__ float part[256];

    if (tid < EDIM) eqs[tid] = embK[(size_t)q[b] * EDIM + tid];
    __syncthreads();

    // Q: thread (d = tid>>2, seg = tid&3) -> 16-wide partial
    {
        const int d = tid >> 2, s = tid & 3;
        const float4* wrow = reinterpret_cast<const float4*>(Wq_w + (size_t)d * EDIM) + s * 4;
        float acc = 0.f;
        #pragma unroll
        for (int i = 0; i < 4; i++) {
            const float4 w4 = wrow[i];
            const int e = s * 16 + i * 4;
            acc += w4.x * eqs[e] + w4.y * eqs[e + 1] + w4.z * eqs[e + 2] + w4.w * eqs[e + 3];
        }
        part[tid] = acc;
    }
    __syncthreads();
    if (tid < DDIM)
        Qs[tid] = part[tid * 4] + part[tid * 4 + 1] + part[tid * 4 + 2] + part[tid * 4 + 3]
                + Wq_b[tid];
    __syncthreads();

    // Qk (tid<128) and SV (tid>=128) together; 2-way d-split; coalesced columns
    {
        const int e    = tid & 63;
        const int half = (tid >> 6) & 1;
        const float* col = Wk_w + ((tid < 128) ? (64 + e) : e);
        float acc = 0.f;
        #pragma unroll
        for (int i = 0; i < 32; i++) {
            const int d = half * 32 + i;
            acc = fmaf(col[(size_t)d * 128], Qs[d], acc);
        }
        part[tid] = acc;
    }
    __syncthreads();
    if (tid < EDIM)
        g_Qk[b * EDIM + tid] = (part[tid] + part[tid + 64]) * 0.125f;
    else if (tid >= 128 && tid < 192)
        g_EV[b * NVAL + (tid - 128)] = __expf((part[tid] + part[tid + 64]) * 0.125f);
}

// ---------------------------------------------------------------------------
// A2: EK. grid = 64 batches x 17 tiles = 1088 independent blocks, 128 threads.
// Coalesced-staged 64-row embK tile (padded shared), Qk from L2 (broadcast),
// one reduction, exp, coalesced 256B write. No sequential tile loop.
// ---------------------------------------------------------------------------
__global__ __launch_bounds__(128) void ek_kernel(const float* __restrict__ embK)
{
    const int bid  = blockIdx.x;
    const int b    = bid / NTILE;
    const int tile = bid % NTILE;
    const int v0   = tile * 64;
    const int tid  = threadIdx.x;
    const int v    = tid & 63;
    const int h    = tid >> 6;

    __shared__ float qks[EDIM];
    __shared__ float tl[64 * 65];     // padded: (v + c) % 32 banks, conflict-free
    __shared__ float part[128];

    if (tid < EDIM) qks[tid] = g_Qk[b * EDIM + tid];
    // Coalesced tile load (independent of qks load)
    {
        const float4* src = reinterpret_cast<const float4*>(embK + (size_t)v0 * EDIM);
        for (int i = tid; i < 1024; i += 128) {
            const float4 val = src[i];
            float* d = &tl[(i >> 4) * 65 + (i & 15) * 4];
            d[0] = val.x; d[1] = val.y; d[2] = val.z; d[3] = val.w;
        }
    }
    __syncthreads();

    float acc = 0.f;
    #pragma unroll
    for (int i = 0; i < 32; i++)
        acc = fmaf(tl[v * 65 + h * 32 + i], qks[h * 32 + i], acc);
    part[tid] = acc;
    __syncthreads();

    if (tid < 64)
        g_EK[(size_t)b * VOCAB + v0 + tid] = __expf(part[tid] + part[tid + 64]);
}

// ---------------------------------------------------------------------------
// Kernel B: gather-histogram, R8 mainloop (measured best), lean REDG epilogue.
// grid = 64 batches x 8 splits (512 blocks), 256 threads, 4 elems/thread.
// Per-block bins accumulate straight into g_num via atomicAdd (REDG);
// last block per batch normalizes and self-resets g_num/g_cnt.
// ---------------------------------------------------------------------------
__global__ __launch_bounds__(256) void attn_kernel(
    const int* __restrict__ x,
    float*     __restrict__ out)
{
    const int b    = blockIdx.x >> 3;
    const int sp   = blockIdx.x & 7;
    const int tid  = threadIdx.x;
    const int warp = tid >> 5;

    __shared__ float EKs[VOCAB];
    __shared__ float bins[8][NVAL];     // warp-replicated histograms
    __shared__ float num[NVAL];
    __shared__ float rcpZ;
    __shared__ int   lastFlag;

    // Prefetch index data first (DRAM) — overlaps table fill (L2)
    const int* kp = x + (size_t)b * 2 * SL + sp * CHUNK;
    const int* vp = kp + SL;
    const int4 k4 = __ldg(reinterpret_cast<const int4*>(kp) + tid);
    const int4 w4 = __ldg(reinterpret_cast<const int4*>(vp) + tid);

    // EK table fill (vectorized, from L2)
    {
        const float4* src = reinterpret_cast<const float4*>(g_EK + (size_t)b * VOCAB);
        float4* dst = reinterpret_cast<float4*>(EKs);
        for (int i = tid; i < VOCAB / 4; i += 256) dst[i] = src[i];
    }
    for (int i = tid; i < 8 * NVAL; i += 256) (&bins[0][0])[i] = 0.f;
    __syncthreads();

    const int kk[EPT] = {k4.x, k4.y, k4.z, k4.w};
    const int vv[EPT] = {w4.x - NVAL, w4.y - NVAL, w4.z - NVAL, w4.w - NVAL};

    #pragma unroll
    for (int i = 0; i < EPT; i++)
        atomicAdd(&bins[warp][vv[i]], EKs[kk[i]]);
    __syncthreads();

    // Block bins -> global accumulator (REDG, no return value used)
    if (tid < NVAL) {
        float bsum = 0.f;
        #pragma unroll
        for (int w = 0; w < 8; w++) bsum += bins[w][tid];
        atomicAdd(&g_num[b * NVAL + tid], bsum);
    }
    __syncthreads();

    if (tid == 0) {
        __threadfence();                            // order REDGs before count
        const int old = atomicAdd(&g_cnt[b], 1);
        lastFlag = (old == SPLIT - 1) ? 1 : 0;
        __threadfence();                            // acquire
    }
    __syncthreads();

    if (lastFlag) {
        if (tid < NVAL) {
            volatile float* vnum = g_num + b * NVAL;
            num[tid] = vnum[tid] * g_EV[b * NVAL + tid];
        }
        __syncthreads();
        if (tid < 32) {
            float zz = num[tid] + num[tid + 32];
            #pragma unroll
            for (int o = 16; o > 0; o >>= 1) zz += __shfl_xor_sync(0xffffffffu, zz, o);
            if (tid == 0) rcpZ = __frcp_rn(zz);
        }
        __syncthreads();
        if (tid < NVAL) {
            out[b * NVAL + tid] = num[tid] * rcpZ;
            g_num[b * NVAL + tid] = 0.f;            // re-arm accumulator
        }
        __syncthreads();
        if (tid == 0) g_cnt[b] = 0;                 // re-arm counter
    }
}

// ---------------------------------------------------------------------------
// Inputs (metadata order): x(int32), q(int32), embK, Wk_w, Wk_b, Wq_w, Wq_b.
// Wk_b is softmax-invariant (constant per batch) and intentionally unused.
// ---------------------------------------------------------------------------
extern "C" void kernel_launch(void* const* d_in, const int* in_sizes, int n_in,
                              void* d_out, int out_size)
{
    const int*   x    = (const int*)  d_in[0];
    const int*   q    = (const int*)  d_in[1];
    const float* embK = (const float*)d_in[2];
    const float* Wk_w = (const float*)d_in[3];
    const float* Wq_w = (const float*)d_in[5];
    const float* Wq_b = (const float*)d_in[6];
    float* out = (float*)d_out;

    qk_kernel<<<BS, 256>>>(q, embK, Wk_w, Wq_w, Wq_b);
    ek_kernel<<<BS * NTILE, 128>>>(embK);
    attn_kernel<<<BS * SPLIT, 256>>>(x, out);
}